// round 1
// baseline (speedup 1.0000x reference)
#include <cuda_runtime.h>

// HybridQuanvolutionFraudNet: reference ends with
//     logits = h @ wf.T + bf            # shape [B, 1]
//     return jax.nn.log_softmax(logits, axis=-1)
// log_softmax over a size-1 axis is identically (and exactly) 0.0.
// All upstream computation (quanvolution statevector sim + MLP) is dead.
// Output = zeros([B, 1]) = out_size float32 zeros.

__global__ void zero_out_kernel(float* __restrict__ out, int n) {
    int i = (blockIdx.x * blockDim.x + threadIdx.x) * 4;
    if (i + 3 < n) {
        // vectorized 16B store
        *reinterpret_cast<float4*>(out + i) = make_float4(0.f, 0.f, 0.f, 0.f);
    } else {
        for (int j = i; j < n; ++j) out[j] = 0.f;
    }
}

extern "C" void kernel_launch(void* const* d_in, const int* in_sizes, int n_in,
                              void* d_out, int out_size) {
    (void)d_in; (void)in_sizes; (void)n_in;
    float* out = (float*)d_out;
    int vec = (out_size + 3) / 4;           // threads, each writing 4 floats
    int block = 256;
    int grid = (vec + block - 1) / block;   // out_size=2048 -> 512 threads -> 2 blocks
    zero_out_kernel<<<grid, block>>>(out, out_size);
}